// round 2
// baseline (speedup 1.0000x reference)
#include <cuda_runtime.h>
#include <cstddef>

#define DIM 1024
#define HID 512
#define NEXP 16
#define TOPK 4
#define MAXT 2048
#define NEXP1 17   // 16 routed + 1 shared expert (weight 1, all tokens)

// ---------------- device scratch (no allocations allowed) ----------------
__device__ int   g_counts[NEXP1];
__device__ int   g_pair_token[NEXP1 * MAXT];
__device__ float g_pair_weight[NEXP1 * MAXT];
__device__ float g_act[(size_t)NEXP1 * MAXT * HID];   // ~71 MB

// ---------------- init: reset per-expert counters ----------------
__global__ void init_kernel(int T) {
    int i = threadIdx.x;
    if (i < NEXP) g_counts[i] = 0;
    else if (i == NEXP) g_counts[NEXP] = T;   // shared expert takes all tokens
}

// ---------------- router: logits -> top4 softmax -> scatter pairs ----------------
__global__ void router_kernel(const float* __restrict__ x,
                              const float* __restrict__ gw, int T) {
    int t = blockIdx.x;
    __shared__ float xs[DIM];
    __shared__ float logits[NEXP];
    const float* xr = x + (size_t)t * DIM;
    for (int k = threadIdx.x; k < DIM; k += blockDim.x) xs[k] = xr[k];
    __syncthreads();

    int e = threadIdx.x >> 4;
    int l = threadIdx.x & 15;
    const float* w = gw + (size_t)e * DIM;
    float s = 0.f;
    for (int k = l; k < DIM; k += 16) s += xs[k] * w[k];
    for (int off = 8; off; off >>= 1) s += __shfl_down_sync(0xffffffffu, s, off, 16);
    if (l == 0) logits[e] = s;
    __syncthreads();

    if (threadIdx.x == 0) {
        float lv[NEXP];
        #pragma unroll
        for (int i = 0; i < NEXP; i++) lv[i] = logits[i];
        int   idx[TOPK];
        float val[TOPK];
        #pragma unroll
        for (int k = 0; k < TOPK; k++) {
            int bi = 0; float bv = -1e30f;
            #pragma unroll
            for (int i = 0; i < NEXP; i++) if (lv[i] > bv) { bv = lv[i]; bi = i; }
            idx[k] = bi; val[k] = bv; lv[bi] = -1e30f;
        }
        // renormalized top-k softmax == softmax over top-k logits
        float m = val[0];
        float wv[TOPK], sum = 0.f;
        #pragma unroll
        for (int k = 0; k < TOPK; k++) { wv[k] = __expf(val[k] - m); sum += wv[k]; }
        float inv = 1.f / sum;
        #pragma unroll
        for (int k = 0; k < TOPK; k++) {
            int ee = idx[k];
            int slot = atomicAdd(&g_counts[ee], 1);
            g_pair_token[ee * MAXT + slot]  = t;
            g_pair_weight[ee * MAXT + slot] = wv[k] * inv;
        }
        // shared expert pair
        g_pair_token[NEXP * MAXT + t]  = t;
        g_pair_weight[NEXP * MAXT + t] = 1.f;
    }
}

// ---------------- GEMM1: act = silu(x@W1^T) * (x@W3^T), gathered rows ----------------
// Tile: 128 tokens x 64 hid, BK=16, 256 threads, 8x4 per thread, dual accumulators.
#define XS_LD 132   // 128 + 4 pad (keeps float4 alignment, 2-way conflicts max)
#define WS_LD 68    // 64 + 4 pad

__global__ __launch_bounds__(256) void gemm1_kernel(
    const float* __restrict__ x,
    const float* __restrict__ w1, const float* __restrict__ w3,
    const float* __restrict__ sw1, const float* __restrict__ sw3)
{
    int e   = blockIdx.z;
    int cnt = g_counts[e];
    int m0  = blockIdx.x * 128;
    if (m0 >= cnt) return;
    int n0  = blockIdx.y * 64;

    const float* W1 = (e < NEXP) ? w1 + (size_t)e * HID * DIM : sw1;
    const float* W3 = (e < NEXP) ? w3 + (size_t)e * HID * DIM : sw3;

    __shared__ float Xs[16 * XS_LD];
    __shared__ float W1s[16 * WS_LD];
    __shared__ float W3s[16 * WS_LD];
    __shared__ int   toks[128];

    int tid = threadIdx.x;
    if (tid < 128) {
        int m = m0 + tid;
        toks[tid] = (m < cnt) ? g_pair_token[e * MAXT + m] : g_pair_token[e * MAXT];
    }

    float acc1[8][4], acc3[8][4];
    #pragma unroll
    for (int i = 0; i < 8; i++)
        #pragma unroll
        for (int j = 0; j < 4; j++) { acc1[i][j] = 0.f; acc3[i][j] = 0.f; }

    int tx = tid & 15, ty = tid >> 4;
    int m_l = tid >> 1, kq = (tid & 1) * 8;   // X loading coords
    int n_l = tid >> 2, kb = (tid & 3) * 4;   // W loading coords

    for (int k0 = 0; k0 < DIM; k0 += 16) {
        __syncthreads();
        // X tile: each thread loads 8 consecutive floats of one token row
        {
            int tok = toks[m_l];
            const float4* src = (const float4*)(x + (size_t)tok * DIM + k0 + kq);
            float4 v0 = src[0], v1 = src[1];
            float* d = &Xs[kq * XS_LD + m_l];
            d[0*XS_LD] = v0.x; d[1*XS_LD] = v0.y; d[2*XS_LD] = v0.z; d[3*XS_LD] = v0.w;
            d[4*XS_LD] = v1.x; d[5*XS_LD] = v1.y; d[6*XS_LD] = v1.z; d[7*XS_LD] = v1.w;
        }
        // W tiles
        {
            float4 a = *(const float4*)(W1 + (size_t)(n0 + n_l) * DIM + k0 + kb);
            W1s[(kb+0)*WS_LD + n_l] = a.x; W1s[(kb+1)*WS_LD + n_l] = a.y;
            W1s[(kb+2)*WS_LD + n_l] = a.z; W1s[(kb+3)*WS_LD + n_l] = a.w;
            float4 b = *(const float4*)(W3 + (size_t)(n0 + n_l) * DIM + k0 + kb);
            W3s[(kb+0)*WS_LD + n_l] = b.x; W3s[(kb+1)*WS_LD + n_l] = b.y;
            W3s[(kb+2)*WS_LD + n_l] = b.z; W3s[(kb+3)*WS_LD + n_l] = b.w;
        }
        __syncthreads();

        #pragma unroll
        for (int kk = 0; kk < 16; kk++) {
            float4 x0 = *(const float4*)&Xs[kk * XS_LD + ty * 8];
            float4 x1 = *(const float4*)&Xs[kk * XS_LD + ty * 8 + 4];
            float4 b1 = *(const float4*)&W1s[kk * WS_LD + tx * 4];
            float4 b3 = *(const float4*)&W3s[kk * WS_LD + tx * 4];
            float xa[8] = {x0.x, x0.y, x0.z, x0.w, x1.x, x1.y, x1.z, x1.w};
            float v1[4] = {b1.x, b1.y, b1.z, b1.w};
            float v3[4] = {b3.x, b3.y, b3.z, b3.w};
            #pragma unroll
            for (int i = 0; i < 8; i++)
                #pragma unroll
                for (int j = 0; j < 4; j++) {
                    acc1[i][j] += xa[i] * v1[j];
                    acc3[i][j] += xa[i] * v3[j];
                }
        }
    }

    // epilogue: silu(h1)*h3 -> act scratch
    #pragma unroll
    for (int i = 0; i < 8; i++) {
        int gm = m0 + ty * 8 + i;
        if (gm < cnt) {
            float4 o;
            float h;
            h = acc1[i][0]; o.x = (h / (1.f + __expf(-h))) * acc3[i][0];
            h = acc1[i][1]; o.y = (h / (1.f + __expf(-h))) * acc3[i][1];
            h = acc1[i][2]; o.z = (h / (1.f + __expf(-h))) * acc3[i][2];
            h = acc1[i][3]; o.w = (h / (1.f + __expf(-h))) * acc3[i][3];
            *(float4*)&g_act[(size_t)(e * MAXT + gm) * HID + n0 + tx * 4] = o;
        }
    }
}

// ---------------- GEMM2: out[token] += weight * (act @ W2^T) ----------------
__global__ __launch_bounds__(256) void gemm2_kernel(
    float* __restrict__ out,
    const float* __restrict__ w2, const float* __restrict__ sw2)
{
    int e   = blockIdx.z;
    int cnt = g_counts[e];
    int m0  = blockIdx.x * 128;
    if (m0 >= cnt) return;
    int n0  = blockIdx.y * 64;

    const float* W2 = (e < NEXP) ? w2 + (size_t)e * DIM * HID : sw2;

    __shared__ float Xs[16 * XS_LD];
    __shared__ float Ws[16 * WS_LD];
    __shared__ int   toks[128];
    __shared__ float wts[128];

    int tid = threadIdx.x;
    if (tid < 128) {
        int m = m0 + tid;
        bool v = (m < cnt);
        toks[tid] = v ? g_pair_token[e * MAXT + m]  : 0;
        wts[tid]  = v ? g_pair_weight[e * MAXT + m] : 0.f;
    }

    float acc[8][4];
    #pragma unroll
    for (int i = 0; i < 8; i++)
        #pragma unroll
        for (int j = 0; j < 4; j++) acc[i][j] = 0.f;

    int tx = tid & 15, ty = tid >> 4;
    int m_l = tid >> 1, kq = (tid & 1) * 8;
    int n_l = tid >> 2, kb = (tid & 3) * 4;

    const float* act_base = &g_act[(size_t)(e * MAXT + m0) * HID];

    for (int k0 = 0; k0 < HID; k0 += 16) {
        __syncthreads();
        {
            const float4* src = (const float4*)(act_base + (size_t)m_l * HID + k0 + kq);
            float4 v0 = src[0], v1 = src[1];
            float* d = &Xs[kq * XS_LD + m_l];
            d[0*XS_LD] = v0.x; d[1*XS_LD] = v0.y; d[2*XS_LD] = v0.z; d[3*XS_LD] = v0.w;
            d[4*XS_LD] = v1.x; d[5*XS_LD] = v1.y; d[6*XS_LD] = v1.z; d[7*XS_LD] = v1.w;
        }
        {
            float4 a = *(const float4*)(W2 + (size_t)(n0 + n_l) * HID + k0 + kb);
            Ws[(kb+0)*WS_LD + n_l] = a.x; Ws[(kb+1)*WS_LD + n_l] = a.y;
            Ws[(kb+2)*WS_LD + n_l] = a.z; Ws[(kb+3)*WS_LD + n_l] = a.w;
        }
        __syncthreads();

        #pragma unroll
        for (int kk = 0; kk < 16; kk++) {
            float4 x0 = *(const float4*)&Xs[kk * XS_LD + ty * 8];
            float4 x1 = *(const float4*)&Xs[kk * XS_LD + ty * 8 + 4];
            float4 bv = *(const float4*)&Ws[kk * WS_LD + tx * 4];
            float xa[8] = {x0.x, x0.y, x0.z, x0.w, x1.x, x1.y, x1.z, x1.w};
            float vb[4] = {bv.x, bv.y, bv.z, bv.w};
            #pragma unroll
            for (int i = 0; i < 8; i++)
                #pragma unroll
                for (int j = 0; j < 4; j++) acc[i][j] += xa[i] * vb[j];
        }
    }

    #pragma unroll
    for (int i = 0; i < 8; i++) {
        int lm = ty * 8 + i;
        int gm = m0 + lm;
        if (gm < cnt) {
            int   tok = toks[lm];
            float wgt = wts[lm];
            float* op = out + (size_t)tok * DIM + n0 + tx * 4;
            atomicAdd(op + 0, acc[i][0] * wgt);
            atomicAdd(op + 1, acc[i][1] * wgt);
            atomicAdd(op + 2, acc[i][2] * wgt);
            atomicAdd(op + 3, acc[i][3] * wgt);
        }
    }
}

// ---------------- launch ----------------
extern "C" void kernel_launch(void* const* d_in, const int* in_sizes, int n_in,
                              void* d_out, int out_size) {
    const float* x    = (const float*)d_in[0];
    const float* gate = (const float*)d_in[1];
    const float* w1   = (const float*)d_in[2];
    const float* w3   = (const float*)d_in[3];
    const float* w2   = (const float*)d_in[4];
    const float* sw1  = (const float*)d_in[5];
    const float* sw3  = (const float*)d_in[6];
    const float* sw2  = (const float*)d_in[7];
    float* out = (float*)d_out;

    int T = in_sizes[0] / DIM;   // 2048

    cudaMemsetAsync(out, 0, (size_t)out_size * sizeof(float));
    init_kernel<<<1, 32>>>(T);
    router_kernel<<<T, 256>>>(x, gate, T);

    dim3 g1(MAXT / 128, HID / 64, NEXP1);
    gemm1_kernel<<<g1, 256>>>(x, w1, w3, sw1, sw3);

    dim3 g2(MAXT / 128, DIM / 64, NEXP1);
    gemm2_kernel<<<g2, 256>>>(out, w2, sw2);
}

// round 7
// speedup vs baseline: 2.0375x; 2.0375x over previous
#include <cuda_runtime.h>
#include <cuda_bf16.h>
#include <cstdint>
#include <cstddef>

#define DIM 1024
#define HID 512
#define NEXP 16
#define TOPK 4
#define MAXT 2048
#define NEXP1 17

// ======================= device scratch (no allocs allowed) =======================
__device__ __nv_bfloat16 g_xh[MAXT * DIM], g_xl[MAXT * DIM];
__device__ __nv_bfloat16 g_w1h[NEXP * HID * DIM], g_w1l[NEXP * HID * DIM];
__device__ __nv_bfloat16 g_w3h[NEXP * HID * DIM], g_w3l[NEXP * HID * DIM];
__device__ __nv_bfloat16 g_w2h[NEXP * DIM * HID], g_w2l[NEXP * DIM * HID];
__device__ __nv_bfloat16 g_sw1h[HID * DIM], g_sw1l[HID * DIM];
__device__ __nv_bfloat16 g_sw3h[HID * DIM], g_sw3l[HID * DIM];
__device__ __nv_bfloat16 g_sw2h[DIM * HID], g_sw2l[DIM * HID];
__device__ __nv_bfloat16 g_acth[NEXP1 * MAXT * HID], g_actl[NEXP1 * MAXT * HID];
__device__ float g_eout[(size_t)NEXP1 * MAXT * DIM];
__device__ int   g_counts[NEXP1];
__device__ int   g_pair_token[NEXP1 * MAXT];
__device__ int   g_tok_pair[MAXT * 5];
__device__ float g_tok_wt[MAXT * 5];

// ======================= helpers =======================
__device__ __forceinline__ uint32_t smem_u32(const void* p) {
    uint32_t a;
    asm("{ .reg .u64 t; cvta.to.shared.u64 t, %1; cvt.u32.u64 %0, t; }" : "=r"(a) : "l"(p));
    return a;
}
__device__ __forceinline__ void cp16(uint32_t s, const void* g) {
    asm volatile("cp.async.cg.shared.global [%0], [%1], 16;" :: "r"(s), "l"(g));
}
#define CP_COMMIT() asm volatile("cp.async.commit_group;" ::: "memory")
#define CP_WAIT1()  asm volatile("cp.async.wait_group 1;" ::: "memory")
#define CP_WAIT0()  asm volatile("cp.async.wait_group 0;" ::: "memory")

__device__ __forceinline__ void ldsm4(uint32_t* r, uint32_t addr) {
    asm volatile("ldmatrix.sync.aligned.m8n8.x4.shared.b16 {%0,%1,%2,%3}, [%4];"
                 : "=r"(r[0]), "=r"(r[1]), "=r"(r[2]), "=r"(r[3]) : "r"(addr));
}
__device__ __forceinline__ void mma16816(float* c, const uint32_t* a, const uint32_t* b) {
    asm volatile(
        "mma.sync.aligned.m16n8k16.row.col.f32.bf16.bf16.f32 "
        "{%0,%1,%2,%3}, {%4,%5,%6,%7}, {%8,%9}, {%0,%1,%2,%3};"
        : "+f"(c[0]), "+f"(c[1]), "+f"(c[2]), "+f"(c[3])
        : "r"(a[0]), "r"(a[1]), "r"(a[2]), "r"(a[3]), "r"(b[0]), "r"(b[1]));
}

// smem tile pitch: 64 bf16 cols + 8 pad = 72 b16 = 144 bytes (conflict-free ldmatrix)
#define PITCH 144
#define A_BYTES  (128 * PITCH)   // 18432
#define B64_BYTES (64 * PITCH)   //  9216
#define STAGE1 (A_BYTES + 2 * B64_BYTES)  // gemm1 stage: 36864
#define STAGE2 (2 * A_BYTES)              // gemm2 stage: 36864
#define SMEM_DYN (2 * STAGE1)             // 73728

// ======================= init / router =======================
__global__ void init_kernel(int T) {
    int i = threadIdx.x;
    if (i < NEXP) g_counts[i] = 0;
    else if (i == NEXP) g_counts[NEXP] = T;
}

__global__ void router_kernel(const float* __restrict__ x,
                              const float* __restrict__ gw, int T) {
    int t = blockIdx.x;
    __shared__ float xs[DIM];
    __shared__ float logits[NEXP];
    const float* xr = x + (size_t)t * DIM;
    for (int k = threadIdx.x; k < DIM; k += blockDim.x) xs[k] = xr[k];
    __syncthreads();

    int e = threadIdx.x >> 4;
    int l = threadIdx.x & 15;
    const float* w = gw + (size_t)e * DIM;
    float s = 0.f;
    for (int k = l; k < DIM; k += 16) s += xs[k] * w[k];
    for (int off = 8; off; off >>= 1) s += __shfl_down_sync(0xffffffffu, s, off, 16);
    if (l == 0) logits[e] = s;
    __syncthreads();

    if (threadIdx.x == 0) {
        float lv[NEXP];
        #pragma unroll
        for (int i = 0; i < NEXP; i++) lv[i] = logits[i];
        int   idx[TOPK];
        float val[TOPK];
        #pragma unroll
        for (int k = 0; k < TOPK; k++) {
            int bi = 0; float bv = -1e30f;
            #pragma unroll
            for (int i = 0; i < NEXP; i++) if (lv[i] > bv) { bv = lv[i]; bi = i; }
            idx[k] = bi; val[k] = bv; lv[bi] = -1e30f;
        }
        float m = val[0];
        float wv[TOPK], sum = 0.f;
        #pragma unroll
        for (int k = 0; k < TOPK; k++) { wv[k] = __expf(val[k] - m); sum += wv[k]; }
        float inv = 1.f / sum;
        #pragma unroll
        for (int k = 0; k < TOPK; k++) {
            int ee = idx[k];
            int slot = atomicAdd(&g_counts[ee], 1);
            g_pair_token[ee * MAXT + slot] = t;
            g_tok_pair[t * 5 + k] = ee * MAXT + slot;
            g_tok_wt[t * 5 + k]   = wv[k] * inv;
        }
        g_pair_token[NEXP * MAXT + t] = t;
        g_tok_pair[t * 5 + 4] = NEXP * MAXT + t;
        g_tok_wt[t * 5 + 4]   = 1.f;
    }
}

// ======================= fp32 -> bf16 hi/lo split =======================
__global__ void split_kernel(const float* __restrict__ src, int which, int n) {
    __nv_bfloat16 *hi, *lo;
    switch (which) {
        case 0: hi = g_xh;  lo = g_xl;  break;
        case 1: hi = g_w1h; lo = g_w1l; break;
        case 2: hi = g_w3h; lo = g_w3l; break;
        case 3: hi = g_w2h; lo = g_w2l; break;
        case 4: hi = g_sw1h; lo = g_sw1l; break;
        case 5: hi = g_sw3h; lo = g_sw3l; break;
        default: hi = g_sw2h; lo = g_sw2l; break;
    }
    int i = (blockIdx.x * blockDim.x + threadIdx.x) * 4;
    if (i < n) {
        float4 v = *(const float4*)(src + i);
        __nv_bfloat16 h0 = __float2bfloat16(v.x), h1 = __float2bfloat16(v.y);
        __nv_bfloat16 h2 = __float2bfloat16(v.z), h3 = __float2bfloat16(v.w);
        __nv_bfloat162 H0; H0.x = h0; H0.y = h1;
        __nv_bfloat162 H1; H1.x = h2; H1.y = h3;
        *(__nv_bfloat162*)(hi + i)     = H0;
        *(__nv_bfloat162*)(hi + i + 2) = H1;
        __nv_bfloat162 L0, L1;
        L0.x = __float2bfloat16(v.x - __bfloat162float(h0));
        L0.y = __float2bfloat16(v.y - __bfloat162float(h1));
        L1.x = __float2bfloat16(v.z - __bfloat162float(h2));
        L1.y = __float2bfloat16(v.w - __bfloat162float(h3));
        *(__nv_bfloat162*)(lo + i)     = L0;
        *(__nv_bfloat162*)(lo + i + 2) = L1;
    }
}

// ======================= GEMM1: act = silu(x@W1^T)*(x@W3^T)  (mma.sync) =======================
// CTA: 128 gathered tokens x (64 w1-cols + 64 w3-cols), BK=64, 3 hi/lo passes (NC=48)
__global__ __launch_bounds__(256) void gemm1_mma() {
    int e   = blockIdx.z;
    int cnt = g_counts[e];
    int m0  = blockIdx.x * 128;
    if (m0 >= cnt) return;
    int n0  = blockIdx.y * 64;

    extern __shared__ __align__(128) char dsm[];
    uint32_t sbase = smem_u32(dsm);
    __shared__ int toks[128];

    int tid  = threadIdx.x;
    int w    = tid >> 5;
    int lane = tid & 31;

    if (tid < 128) {
        int m = m0 + tid;
        toks[tid] = (m < cnt) ? g_pair_token[e * MAXT + m] : g_pair_token[e * MAXT];
    }
    __syncthreads();

    const __nv_bfloat16* Ap[3] = { g_xh, g_xh, g_xl };
    const __nv_bfloat16 *w1H, *w1L, *w3H, *w3L;
    if (e < NEXP) {
        size_t off = (size_t)e * HID * DIM;
        w1H = g_w1h + off; w1L = g_w1l + off;
        w3H = g_w3h + off; w3L = g_w3l + off;
    } else { w1H = g_sw1h; w1L = g_sw1l; w3H = g_sw3h; w3L = g_sw3l; }
    const __nv_bfloat16* B1p[3] = { w1H, w1L, w1H };
    const __nv_bfloat16* B3p[3] = { w3H, w3L, w3H };

    float acc[2][8][4];
    #pragma unroll
    for (int h = 0; h < 2; h++)
        #pragma unroll
        for (int j = 0; j < 8; j++)
            #pragma unroll
            for (int q = 0; q < 4; q++) acc[h][j][q] = 0.f;

    // loader index precompute
    int lrowA = tid >> 3, lcvA = tid & 7;   // + i*32 rows

    // ldmatrix address components
    int mrow = (w >> 1) * 32;
    int ncl  = (w & 1) * 32;
    int aRow = (lane & 7) + ((lane >> 3) & 1) * 8;   // + h*16 + mrow
    int aK   = (lane >> 4) * 8;
    int bRow = (lane & 7) + (lane >> 4) * 8;         // + group n base
    int bK   = ((lane >> 3) & 1) * 8;

    const int NC = 48;
    // prologue: chunk 0 -> buf 0
    {
        int p = 0, k0 = 0;
        #pragma unroll
        for (int i = 0; i < 4; i++) {
            int row = lrowA + i * 32;
            cp16(sbase + row * PITCH + lcvA * 16,
                 (const char*)(Ap[p] + (size_t)toks[row] * DIM + k0) + lcvA * 16);
        }
        #pragma unroll
        for (int i = 0; i < 2; i++) {
            int row = lrowA + i * 32;
            cp16(sbase + A_BYTES + row * PITCH + lcvA * 16,
                 (const char*)(B1p[p] + (size_t)(n0 + row) * DIM + k0) + lcvA * 16);
            cp16(sbase + A_BYTES + B64_BYTES + row * PITCH + lcvA * 16,
                 (const char*)(B3p[p] + (size_t)(n0 + row) * DIM + k0) + lcvA * 16);
        }
        CP_COMMIT();
    }

    for (int c = 0; c < NC; c++) {
        if (c + 1 < NC) {
            int cn = c + 1;
            int p = cn >> 4, k0 = (cn & 15) * 64;
            uint32_t buf = sbase + (cn & 1) * STAGE1;
            #pragma unroll
            for (int i = 0; i < 4; i++) {
                int row = lrowA + i * 32;
                cp16(buf + row * PITCH + lcvA * 16,
                     (const char*)(Ap[p] + (size_t)toks[row] * DIM + k0) + lcvA * 16);
            }
            #pragma unroll
            for (int i = 0; i < 2; i++) {
                int row = lrowA + i * 32;
                cp16(buf + A_BYTES + row * PITCH + lcvA * 16,
                     (const char*)(B1p[p] + (size_t)(n0 + row) * DIM + k0) + lcvA * 16);
                cp16(buf + A_BYTES + B64_BYTES + row * PITCH + lcvA * 16,
                     (const char*)(B3p[p] + (size_t)(n0 + row) * DIM + k0) + lcvA * 16);
            }
            CP_COMMIT();
            CP_WAIT1();
        } else {
            CP_WAIT0();
        }
        __syncthreads();

        uint32_t buf = sbase + (c & 1) * STAGE1;
        uint32_t Ab  = buf;
        uint32_t Bb[2] = { buf + A_BYTES, buf + A_BYTES + B64_BYTES };

        #pragma unroll
        for (int ks = 0; ks < 4; ks++) {
            int kk = ks * 16;
            uint32_t a[2][4];
            #pragma unroll
            for (int h = 0; h < 2; h++)
                ldsm4(a[h], Ab + (mrow + h * 16 + aRow) * PITCH + (kk + aK) * 2);
            uint32_t b[4][4];
            #pragma unroll
            for (int g = 0; g < 4; g++) {
                uint32_t base = Bb[g >> 1];
                int nloc = ncl + (g & 1) * 16;
                ldsm4(b[g], base + (nloc + bRow) * PITCH + (kk + bK) * 2);
            }
            #pragma unroll
            for (int h = 0; h < 2; h++)
                #pragma unroll
                for (int j = 0; j < 8; j++)
                    mma16816(acc[h][j], a[h], &b[j >> 1][(j & 1) * 2]);
        }
        __syncthreads();
    }

    // epilogue: silu(h1)*h3 -> act hi/lo bf16
    #pragma unroll
    for (int h = 0; h < 2; h++) {
        #pragma unroll
        for (int jj = 0; jj < 4; jj++) {
            int colb = n0 + ncl + jj * 8 + (lane & 3) * 2;
            float* a1 = acc[h][jj];
            float* a3 = acc[h][jj + 4];
            #pragma unroll
            for (int half = 0; half < 2; half++) {
                int r  = mrow + h * 16 + (lane >> 2) + half * 8;
                int gm = m0 + r;
                if (gm < cnt) {
                    float h1a = a1[half * 2],     h3a = a3[half * 2];
                    float h1b = a1[half * 2 + 1], h3b = a3[half * 2 + 1];
                    float v0 = h1a / (1.f + __expf(-h1a)) * h3a;
                    float v1 = h1b / (1.f + __expf(-h1b)) * h3b;
                    __nv_bfloat16 hh0 = __float2bfloat16(v0);
                    __nv_bfloat16 hh1 = __float2bfloat16(v1);
                    __nv_bfloat162 H; H.x = hh0; H.y = hh1;
                    size_t addr = ((size_t)e * MAXT + gm) * HID + colb;
                    *(__nv_bfloat162*)&g_acth[addr] = H;
                    __nv_bfloat162 L;
                    L.x = __float2bfloat16(v0 - __bfloat162float(hh0));
                    L.y = __float2bfloat16(v1 - __bfloat162float(hh1));
                    *(__nv_bfloat162*)&g_actl[addr] = L;
                }
            }
        }
    }
}

// ======================= GEMM2: eout = act @ W2^T (unweighted, mma.sync) =======================
// CTA: 128 pair rows x 128 dim cols, BK=64, 3 passes (NC=24)
__global__ __launch_bounds__(256) void gemm2_mma() {
    int e   = blockIdx.z;
    int cnt = g_counts[e];
    int m0  = blockIdx.x * 128;
    if (m0 >= cnt) return;
    int n0  = blockIdx.y * 128;

    extern __shared__ __align__(128) char dsm[];
    uint32_t sbase = smem_u32(dsm);

    int tid  = threadIdx.x;
    int w    = tid >> 5;
    int lane = tid & 31;

    const __nv_bfloat16* Ap[3] = { g_acth, g_acth, g_actl };
    const __nv_bfloat16 *w2H, *w2L;
    if (e < NEXP) {
        size_t off = (size_t)e * DIM * HID;
        w2H = g_w2h + off; w2L = g_w2l + off;
    } else { w2H = g_sw2h; w2L = g_sw2l; }
    const __nv_bfloat16* Bp[3] = { w2H, w2L, w2H };

    size_t rowbase = (size_t)e * MAXT + m0;

    float acc[2][8][4];
    #pragma unroll
    for (int h = 0; h < 2; h++)
        #pragma unroll
        for (int j = 0; j < 8; j++)
            #pragma unroll
            for (int q = 0; q < 4; q++) acc[h][j][q] = 0.f;

    int lrow = tid >> 3, lcv = tid & 7;

    int mrow = (w >> 1) * 32;
    int ncl  = (w & 1) * 64;
    int aRow = (lane & 7) + ((lane >> 3) & 1) * 8;
    int aK   = (lane >> 4) * 8;
    int bRow = (lane & 7) + (lane >> 4) * 8;
    int bK   = ((lane >> 3) & 1) * 8;

    const int NC = 24;
    {
        int p = 0, k0 = 0;
        #pragma unroll
        for (int i = 0; i < 4; i++) {
            int row = lrow + i * 32;
            cp16(sbase + row * PITCH + lcv * 16,
                 (const char*)(Ap[p] + (rowbase + row) * HID + k0) + lcv * 16);
            cp16(sbase + A_BYTES + row * PITCH + lcv * 16,
                 (const char*)(Bp[p] + (size_t)(n0 + row) * HID + k0) + lcv * 16);
        }
        CP_COMMIT();
    }

    for (int c = 0; c < NC; c++) {
        if (c + 1 < NC) {
            int cn = c + 1;
            int p = cn >> 3, k0 = (cn & 7) * 64;
            uint32_t buf = sbase + (cn & 1) * STAGE2;
            #pragma unroll
            for (int i = 0; i < 4; i++) {
                int row = lrow + i * 32;
                cp16(buf + row * PITCH + lcv * 16,
                     (const char*)(Ap[p] + (rowbase + row) * HID + k0) + lcv * 16);
                cp16(buf + A_BYTES + row * PITCH + lcv * 16,
                     (const char*)(Bp[p] + (size_t)(n0 + row) * HID + k0) + lcv * 16);
            }
            CP_COMMIT();
            CP_WAIT1();
        } else {
            CP_WAIT0();
        }
        __syncthreads();

        uint32_t buf = sbase + (c & 1) * STAGE2;
        uint32_t Ab  = buf;
        uint32_t Bb  = buf + A_BYTES;

        #pragma unroll
        for (int ks = 0; ks < 4; ks++) {
            int kk = ks * 16;
            uint32_t a[2][4];
            #pragma unroll
            for (int h = 0; h < 2; h++)
                ldsm4(a[h], Ab + (mrow + h * 16 + aRow) * PITCH + (kk + aK) * 2);
            uint32_t b[4][4];
            #pragma unroll
            for (int g = 0; g < 4; g++) {
                int nloc = ncl + g * 16;
                ldsm4(b[g], Bb + (nloc + bRow) * PITCH + (kk + bK) * 2);
            }
            #pragma unroll
            for (int h = 0; h < 2; h++)
                #pragma unroll
                for (int j = 0; j < 8; j++)
                    mma16816(acc[h][j], a[h], &b[j >> 1][(j & 1) * 2]);
        }
        __syncthreads();
    }

    // epilogue: write unweighted f32 eout
    #pragma unroll
    for (int h = 0; h < 2; h++) {
        #pragma unroll
        for (int j = 0; j < 8; j++) {
            int col = n0 + ncl + j * 8 + (lane & 3) * 2;
            #pragma unroll
            for (int half = 0; half < 2; half++) {
                int r  = mrow + h * 16 + (lane >> 2) + half * 8;
                int gm = m0 + r;
                if (gm < cnt) {
                    float2 v;
                    v.x = acc[h][j][half * 2];
                    v.y = acc[h][j][half * 2 + 1];
                    *(float2*)&g_eout[((size_t)e * MAXT + gm) * DIM + col] = v;
                }
            }
        }
    }
}

// ======================= combine: out[t] = sum_k w_k * eout[pair_k] =======================
__global__ void combine_kernel(float* __restrict__ out) {
    int t = blockIdx.x;
    int c = threadIdx.x * 4;
    float4 acc = make_float4(0.f, 0.f, 0.f, 0.f);
    #pragma unroll
    for (int k = 0; k < 5; k++) {
        int   pr = g_tok_pair[t * 5 + k];
        float w  = g_tok_wt[t * 5 + k];
        float4 v = *(const float4*)&g_eout[(size_t)pr * DIM + c];
        acc.x += w * v.x; acc.y += w * v.y; acc.z += w * v.z; acc.w += w * v.w;
    }
    *(float4*)&out[(size_t)t * DIM + c] = acc;
}

// ======================= launch =======================
extern "C" void kernel_launch(void* const* d_in, const int* in_sizes, int n_in,
                              void* d_out, int out_size) {
    const float* x    = (const float*)d_in[0];
    const float* gate = (const float*)d_in[1];
    const float* w1   = (const float*)d_in[2];
    const float* w3   = (const float*)d_in[3];
    const float* w2   = (const float*)d_in[4];
    const float* sw1  = (const float*)d_in[5];
    const float* sw3  = (const float*)d_in[6];
    const float* sw2  = (const float*)d_in[7];
    float* out = (float*)d_out;

    int T = in_sizes[0] / DIM;   // 2048

    cudaFuncSetAttribute(gemm1_mma, cudaFuncAttributeMaxDynamicSharedMemorySize, SMEM_DYN);
    cudaFuncSetAttribute(gemm2_mma, cudaFuncAttributeMaxDynamicSharedMemorySize, SMEM_DYN);

    init_kernel<<<1, 32>>>(T);
    router_kernel<<<T, 256>>>(x, gate, T);

    int nx = MAXT * DIM, nw = NEXP * HID * DIM, ns = HID * DIM;
    split_kernel<<<(nx / 4 + 255) / 256, 256>>>(x,   0, nx);
    split_kernel<<<(nw / 4 + 255) / 256, 256>>>(w1,  1, nw);
    split_kernel<<<(nw / 4 + 255) / 256, 256>>>(w3,  2, nw);
    split_kernel<<<(nw / 4 + 255) / 256, 256>>>(w2,  3, nw);
    split_kernel<<<(ns / 4 + 255) / 256, 256>>>(sw1, 4, ns);
    split_kernel<<<(ns / 4 + 255) / 256, 256>>>(sw3, 5, ns);
    split_kernel<<<(ns / 4 + 255) / 256, 256>>>(sw2, 6, ns);

    dim3 g1(MAXT / 128, HID / 64, NEXP1);
    gemm1_mma<<<g1, 256, SMEM_DYN>>>();

    dim3 g2(MAXT / 128, DIM / 128, NEXP1);
    gemm2_mma<<<g2, 256, SMEM_DYN>>>();

    combine_kernel<<<T, DIM / 4>>>(out);
}